// round 13
// baseline (speedup 1.0000x reference)
#include <cuda_runtime.h>
#include <cuda_fp16.h>
#include <math.h>
#include <stdint.h>

#define SQ 2048
#define HD 1024
#define NHEAD 16
#define HNDIM 64
#define NLAYER 2

#define BM 128
#define BK 64      // halves per K-tile (GEMM)
#define LDK 72     // padded A smem row (halves)
#define NST 2      // GEMM pipeline stages

// flash attention tiles
#define FLDQ 72                       // padded row length (halves) for Q/K/V tiles
#define FKVB (128 * FLDQ * 2)         // bytes per 128x64 tile = 18432
#define FSTG (2 * FKVB)               // K+V per stage
#define FSMT (FKVB + 2 * FSTG)        // Q + 2 stages = 92160 B

// ---------------- scratch (device globals; no allocations allowed) ----------
__device__ float g_h[SQ * HD];                 // fp32 residual stream
__device__ __half g_lnb16[SQ * HD];
__device__ __half g_qkv16[SQ * 3 * HD];
__device__ __half g_ctx16[SQ * HD];
__device__ __half g_fc16[SQ * 4 * HD];
// fp16 weights, SAME [K,N] layout as the fp32 originals (convert only)
__device__ __half g_qkvw16[NLAYER * HD * 3 * HD];
__device__ __half g_densew16[NLAYER * HD * HD];
__device__ __half g_fcw16[NLAYER * HD * 4 * HD];
__device__ __half g_projw16[NLAYER * 4 * HD * HD];

// ---------------- helpers ----------------------------------------------------
__device__ __forceinline__ float gelu_f(float x) {
    return 0.5f * x * (1.0f + tanhf(0.7978845608028654f * x * (1.0f + 0.044715f * x * x)));
}

__device__ __forceinline__ void cp16h(uint32_t smem, const __half* g) {
    asm volatile("cp.async.cg.shared.global [%0], [%1], 16;\n" :: "r"(smem), "l"(g));
}

__device__ __forceinline__ void ldsm4(uint32_t* r, uint32_t addr) {
    asm volatile("ldmatrix.sync.aligned.m8n8.x4.shared.b16 {%0,%1,%2,%3}, [%4];"
                 : "=r"(r[0]), "=r"(r[1]), "=r"(r[2]), "=r"(r[3]) : "r"(addr));
}

__device__ __forceinline__ void ldsm4t(uint32_t* r, uint32_t addr) {
    asm volatile("ldmatrix.sync.aligned.m8n8.x4.trans.shared.b16 {%0,%1,%2,%3}, [%4];"
                 : "=r"(r[0]), "=r"(r[1]), "=r"(r[2]), "=r"(r[3]) : "r"(addr));
}

__device__ __forceinline__ void mma16(float* d, const uint32_t* a, const uint32_t* b) {
    asm volatile(
        "mma.sync.aligned.m16n8k16.row.col.f32.f16.f16.f32 "
        "{%0,%1,%2,%3}, {%4,%5,%6,%7}, {%8,%9}, {%0,%1,%2,%3};\n"
        : "+f"(d[0]), "+f"(d[1]), "+f"(d[2]), "+f"(d[3])
        : "r"(a[0]), "r"(a[1]), "r"(a[2]), "r"(a[3]), "r"(b[0]), "r"(b[1]));
}

__device__ __forceinline__ uint32_t packh2(float a, float b) {
    __half2 h = __floats2half2_rn(a, b);
    return *(uint32_t*)&h;
}

// ---------------- layernorm: one-pass, float4 I/O -----------------------------
template <typename OUT>
__global__ __launch_bounds__(256) void ln_kernel(const float* __restrict__ x,
                                                 const float* __restrict__ g,
                                                 const float* __restrict__ b,
                                                 OUT* __restrict__ out) {
    int row = blockIdx.x;
    const float* xr = x + (size_t)row * HD;
    OUT* outr = out + (size_t)row * HD;
    int t = threadIdx.x;
    __shared__ float red1[8], red2[8];

    float4 v = *(const float4*)(xr + t * 4);
    float s1 = v.x + v.y + v.z + v.w;
    float s2 = v.x * v.x + v.y * v.y + v.z * v.z + v.w * v.w;
#pragma unroll
    for (int o = 16; o > 0; o >>= 1) {
        s1 += __shfl_xor_sync(~0u, s1, o);
        s2 += __shfl_xor_sync(~0u, s2, o);
    }
    if ((t & 31) == 0) { red1[t >> 5] = s1; red2[t >> 5] = s2; }
    __syncthreads();
    s1 = 0.0f; s2 = 0.0f;
#pragma unroll
    for (int w = 0; w < 8; w++) { s1 += red1[w]; s2 += red2[w]; }
    float mu = s1 * (1.0f / HD);
    float var = s2 * (1.0f / HD) - mu * mu;
    float rstd = rsqrtf(var + 1e-5f);

    float4 gg = *(const float4*)(g + t * 4);
    float4 bb = *(const float4*)(b + t * 4);
    float o0 = (v.x - mu) * rstd * gg.x + bb.x;
    float o1 = (v.y - mu) * rstd * gg.y + bb.y;
    float o2 = (v.z - mu) * rstd * gg.z + bb.z;
    float o3 = (v.w - mu) * rstd * gg.w + bb.w;
    if (sizeof(OUT) == 2) {
        __half2 h0 = __floats2half2_rn(o0, o1);
        __half2 h1 = __floats2half2_rn(o2, o3);
        *(uint2*)((__half*)outr + t * 4) = make_uint2(*(uint32_t*)&h0, *(uint32_t*)&h1);
    } else {
        *(float4*)((float*)outr + t * 4) = make_float4(o0, o1, o2, o3);
    }
}

// ---------------- fused weight convert: all 4 arrays, one launch --------------
#define W1 ((long long)NLAYER * HD * 3 * HD)   // qkv
#define W2 ((long long)NLAYER * HD * HD)       // dense
#define W3 ((long long)NLAYER * HD * 4 * HD)   // fc
#define W4 ((long long)NLAYER * 4 * HD * HD)   // proj

__global__ __launch_bounds__(256) void convert_all(
    const float* __restrict__ qkv_w, const float* __restrict__ dense_w,
    const float* __restrict__ fc_w, const float* __restrict__ proj_w,
    __half* __restrict__ qkvh, __half* __restrict__ denseh,
    __half* __restrict__ fch, __half* __restrict__ projh) {
    long long i = ((long long)blockIdx.x * 256 + threadIdx.x) * 4;
    const float* src;
    __half* dst;
    if (i < W1) { src = qkv_w; dst = qkvh; }
    else if (i < W1 + W2) { i -= W1; src = dense_w; dst = denseh; }
    else if (i < W1 + W2 + W3) { i -= W1 + W2; src = fc_w; dst = fch; }
    else { i -= W1 + W2 + W3; src = proj_w; dst = projh; }
    float4 v = *(const float4*)(src + i);
    __half2 a = __floats2half2_rn(v.x, v.y);
    __half2 b = __floats2half2_rn(v.z, v.w);
    *(uint2*)(dst + i) = make_uint2(*(uint32_t*)&a, *(uint32_t*)&b);
}

// ---------------- fused flash attention ---------------------------------------
// grid: (SQ/128, NHEAD), block 256 (8 warps x 16 q-rows). KV tile = 128 keys.
// 2-stage, ONE __syncthreads per KV tile.
__global__ __launch_bounds__(256, 1) void flash_attn(
    const __half* __restrict__ qkv, __half* __restrict__ ctx) {
    extern __shared__ __align__(16) char fsm[];
    uint32_t sb;
    asm("{ .reg .u64 tmp; cvta.to.shared.u64 tmp, %1; cvt.u32.u64 %0, tmp; }"
        : "=r"(sb) : "l"(fsm));

    int qt = gridDim.x - 1 - blockIdx.x;   // heavy q-tiles first
    int hh = blockIdx.y;
    int ntiles = qt + 1;

    int t = threadIdx.x, w = t >> 5, lane = t & 31;
    int lrow = lane & 15, lcol = (lane >> 4) << 3;
    int g = lane >> 2, tig = lane & 3;

    const __half* Qg = qkv + (size_t)(qt * 128) * (3 * HD) + hh * HNDIM;
    const __half* Kg = qkv + HD + hh * HNDIM;
    const __half* Vg = qkv + 2 * HD + hh * HNDIM;

#define FLOADKV(j)                                                                 \
    {                                                                              \
        uint32_t base_ = sb + FKVB + ((j) & 1) * FSTG;                             \
        const __half* Kg_ = Kg + (size_t)((j) * 128) * (3 * HD);                   \
        const __half* Vg_ = Vg + (size_t)((j) * 128) * (3 * HD);                   \
        _Pragma("unroll") for (int i_ = 0; i_ < 4; i_++) {                         \
            int id_ = t + i_ * 256;                                                \
            int r_ = id_ >> 3, c_ = (id_ & 7) * 8;                                 \
            cp16h(base_ + (r_ * FLDQ + c_) * 2, Kg_ + (size_t)r_ * (3 * HD) + c_); \
            cp16h(base_ + FKVB + (r_ * FLDQ + c_) * 2,                             \
                  Vg_ + (size_t)r_ * (3 * HD) + c_);                               \
        }                                                                          \
        asm volatile("cp.async.commit_group;\n" ::: "memory");                     \
    }

    // group 0: Q + KV tile 0
#pragma unroll
    for (int i = 0; i < 4; i++) {
        int id = t + i * 256;
        int r = id >> 3, c = (id & 7) * 8;
        cp16h(sb + (r * FLDQ + c) * 2, Qg + (size_t)r * (3 * HD) + c);
    }
    FLOADKV(0);

    float m0 = -1e30f, m1 = -1e30f, l0 = 0.0f, l1 = 0.0f;
    float out[8][4] = {};
    uint32_t aq[4][4];

    int row0 = qt * 128 + w * 16 + g;
    int row1 = row0 + 8;

    for (int j = 0; j < ntiles; j++) {
        asm volatile("cp.async.wait_group 0;\n" ::: "memory");
        __syncthreads();
        if (j + 1 < ntiles) FLOADKV(j + 1);

        if (j == 0) {
#pragma unroll
            for (int kk = 0; kk < 4; kk++)
                ldsm4(aq[kk], sb + ((w * 16 + lrow) * FLDQ + kk * 16 + lcol) * 2);
        }

        uint32_t kb = sb + FKVB + (j & 1) * FSTG;
        uint32_t vb = kb + FKVB;

        // S = Q K^T
        float sacc[16][4] = {};
#pragma unroll
        for (int kk = 0; kk < 4; kk++) {
            uint32_t bk[16][2];
#pragma unroll
            for (int jp = 0; jp < 8; jp++) {
                uint32_t r4[4];
                ldsm4(r4, kb + ((jp * 16 + lrow) * FLDQ + kk * 16 + lcol) * 2);
                bk[2 * jp][0] = r4[0]; bk[2 * jp][1] = r4[2];
                bk[2 * jp + 1][0] = r4[1]; bk[2 * jp + 1][1] = r4[3];
            }
#pragma unroll
            for (int jn = 0; jn < 16; jn++) mma16(sacc[jn], aq[kk], bk[jn]);
        }

        // scale + causal mask + tile row-max
        bool diag = (j == qt);
        float tm0 = -1e30f, tm1 = -1e30f;
#pragma unroll
        for (int jn = 0; jn < 16; jn++) {
            int col = j * 128 + jn * 8 + tig * 2;
            float s0 = sacc[jn][0] * 0.125f, s1 = sacc[jn][1] * 0.125f;
            float s2 = sacc[jn][2] * 0.125f, s3 = sacc[jn][3] * 0.125f;
            if (diag) {
                if (col > row0) s0 = -10000.0f;
                if (col + 1 > row0) s1 = -10000.0f;
                if (col > row1) s2 = -10000.0f;
                if (col + 1 > row1) s3 = -10000.0f;
            }
            sacc[jn][0] = s0; sacc[jn][1] = s1; sacc[jn][2] = s2; sacc[jn][3] = s3;
            tm0 = fmaxf(tm0, fmaxf(s0, s1));
            tm1 = fmaxf(tm1, fmaxf(s2, s3));
        }
        tm0 = fmaxf(tm0, __shfl_xor_sync(~0u, tm0, 1));
        tm0 = fmaxf(tm0, __shfl_xor_sync(~0u, tm0, 2));
        tm1 = fmaxf(tm1, __shfl_xor_sync(~0u, tm1, 1));
        tm1 = fmaxf(tm1, __shfl_xor_sync(~0u, tm1, 2));

        float mn0 = fmaxf(m0, tm0), mn1 = fmaxf(m1, tm1);
        float c0 = __expf(m0 - mn0), c1 = __expf(m1 - mn1);
        l0 *= c0; l1 *= c1;
#pragma unroll
        for (int jo = 0; jo < 8; jo++) {
            out[jo][0] *= c0; out[jo][1] *= c0;
            out[jo][2] *= c1; out[jo][3] *= c1;
        }
        m0 = mn0; m1 = mn1;

        // P = exp(S - m) -> fp16 A-frags
        uint32_t pa[8][4];
#pragma unroll
        for (int kk2 = 0; kk2 < 8; kk2++) {
            float p00 = __expf(sacc[2 * kk2][0] - mn0);
            float p01 = __expf(sacc[2 * kk2][1] - mn0);
            float p02 = __expf(sacc[2 * kk2][2] - mn1);
            float p03 = __expf(sacc[2 * kk2][3] - mn1);
            float p10 = __expf(sacc[2 * kk2 + 1][0] - mn0);
            float p11 = __expf(sacc[2 * kk2 + 1][1] - mn0);
            float p12 = __expf(sacc[2 * kk2 + 1][2] - mn1);
            float p13 = __expf(sacc[2 * kk2 + 1][3] - mn1);
            l0 += p00 + p01 + p10 + p11;
            l1 += p02 + p03 + p12 + p13;
            pa[kk2][0] = packh2(p00, p01);
            pa[kk2][1] = packh2(p02, p03);
            pa[kk2][2] = packh2(p10, p11);
            pa[kk2][3] = packh2(p12, p13);
        }

        // out += P V   (V via ldmatrix.trans from [s][d])
#pragma unroll
        for (int kk2 = 0; kk2 < 8; kk2++) {
            uint32_t bv[8][2];
#pragma unroll
            for (int jp = 0; jp < 4; jp++) {
                uint32_t r4[4];
                ldsm4t(r4, vb + ((kk2 * 16 + lrow) * FLDQ + jp * 16 + lcol) * 2);
                bv[2 * jp][0] = r4[0]; bv[2 * jp][1] = r4[1];
                bv[2 * jp + 1][0] = r4[2]; bv[2 * jp + 1][1] = r4[3];
            }
#pragma unroll
            for (int jo = 0; jo < 8; jo++) mma16(out[jo], pa[kk2], bv[jo]);
        }
    }
#undef FLOADKV

    // finalize
    l0 += __shfl_xor_sync(~0u, l0, 1);
    l0 += __shfl_xor_sync(~0u, l0, 2);
    l1 += __shfl_xor_sync(~0u, l1, 1);
    l1 += __shfl_xor_sync(~0u, l1, 2);
    float r0 = 1.0f / l0, r1 = 1.0f / l1;

#pragma unroll
    for (int jo = 0; jo < 8; jo++) {
        int d = hh * HNDIM + jo * 8 + tig * 2;
        __half2 o0 = __floats2half2_rn(out[jo][0] * r0, out[jo][1] * r0);
        __half2 o1 = __floats2half2_rn(out[jo][2] * r1, out[jo][3] * r1);
        *(__half2*)(ctx + (size_t)row0 * HD + d) = o0;
        *(__half2*)(ctx + (size_t)row1 * HD + d) = o1;
    }
}

// ---------------- fp16 tensor-core GEMM (linear layers) -----------------------
// A [M,K] row-major; B [K,N] row-major (natural weight layout) via ldsm.trans.
// BK=64, 2-stage, ONE __syncthreads per K-tile.
template <int TBN, int OUTH>
__global__ __launch_bounds__(256, 2) void hgemm(
    const __half* __restrict__ A, int lda,
    const __half* __restrict__ B, int ldb,
    const float* __restrict__ bias,
    const float* __restrict__ R,
    void* __restrict__ Cv, int ldc,
    int K, int act) {
    constexpr int NF = TBN / 16;
    constexpr int LDB = TBN + 8;
    constexpr int ASZ = BM * LDK * 2;
    constexpr int BSZ = BK * LDB * 2;
    constexpr int STB = ASZ + BSZ;
    constexpr int A_CP = (BM * BK / 8) / 256;
    constexpr int B_CP = (BK * TBN / 8) / 256;
    constexpr int BCHUNK = TBN / 8;

    extern __shared__ __align__(16) char smem[];
    uint32_t sb;
    asm("{ .reg .u64 tmp; cvta.to.shared.u64 tmp, %1; cvt.u32.u64 %0, tmp; }"
        : "=r"(sb) : "l"(smem));

    int m0 = blockIdx.y * BM;
    int n0 = blockIdx.x * TBN;
    int T = K / BK;

    int t = threadIdx.x;
    int wid = t >> 5, lane = t & 31;
    int g = lane >> 2, tig = lane & 3;
    int wm = (wid & 3) * 32;
    int wn = (wid >> 2) * (TBN / 2);

    const __half* Ag0 = A + (long long)m0 * lda;
    const __half* Bg0 = B + n0;

    float acc[2][NF][4] = {};

#define LOADST(ti)                                                                \
    {                                                                             \
        uint32_t as_ = sb + ((ti) & 1) * STB;                                     \
        uint32_t bs_ = as_ + ASZ;                                                 \
        const __half* Ag_ = Ag0 + (long long)(ti) * BK;                           \
        const __half* Bg_ = Bg0 + (long long)(ti) * BK * ldb;                     \
        _Pragma("unroll") for (int i = 0; i < A_CP; i++) {                        \
            int id = t + i * 256;                                                 \
            int r = id >> 3, c = (id & 7) * 8;                                    \
            cp16h(as_ + (r * LDK + c) * 2, Ag_ + (long long)r * lda + c);         \
        }                                                                         \
        _Pragma("unroll") for (int i = 0; i < B_CP; i++) {                        \
            int id = t + i * 256;                                                 \
            int r = id / BCHUNK, c = (id % BCHUNK) * 8;                           \
            cp16h(bs_ + (r * LDB + c) * 2, Bg_ + (long long)r * ldb + c);         \
        }                                                                         \
        asm volatile("cp.async.commit_group;\n" ::: "memory");                    \
    }

    LOADST(0);

    int lrow = lane & 15, lcol = (lane >> 4) << 3;

    for (int ti = 0; ti < T; ti++) {
        asm volatile("cp.async.wait_group 0;\n" ::: "memory");
        __syncthreads();
        if (ti + 1 < T) LOADST(ti + 1);

        uint32_t as = sb + (ti & 1) * STB;
        uint32_t bs = as + ASZ;

#pragma unroll
        for (int kk = 0; kk < 4; kk++) {
            int k16 = kk * 16;
            uint32_t a[2][4];
#pragma unroll
            for (int f = 0; f < 2; f++)
                ldsm4(a[f], as + ((wm + f * 16 + lrow) * LDK + k16 + lcol) * 2);
            uint32_t bf[NF][2];
#pragma unroll
            for (int jp = 0; jp < NF / 2; jp++) {
                uint32_t r4[4];
                ldsm4t(r4, bs + ((k16 + lrow) * LDB + wn + jp * 16 + lcol) * 2);
                bf[2 * jp][0] = r4[0]; bf[2 * jp][1] = r4[1];
                bf[2 * jp + 1][0] = r4[2]; bf[2 * jp + 1][1] = r4[3];
            }
#pragma unroll
            for (int f = 0; f < 2; f++)
#pragma unroll
                for (int j = 0; j < NF; j++) mma16(acc[f][j], a[f], bf[j]);
        }
    }
#undef LOADST

#pragma unroll
    for (int f = 0; f < 2; f++) {
#pragma unroll
        for (int j = 0; j < NF; j++) {
            int n = n0 + wn + j * 8 + tig * 2;
#pragma unroll
            for (int half_ = 0; half_ < 2; half_++) {
                int m = m0 + wm + f * 16 + g + half_ * 8;
                float v0 = acc[f][j][half_ * 2 + 0];
                float v1 = acc[f][j][half_ * 2 + 1];
                if (bias) {
                    float2 bb = *(const float2*)(bias + n);
                    v0 += bb.x; v1 += bb.y;
                }
                if (act) { v0 = gelu_f(v0); v1 = gelu_f(v1); }
                if (R) {
                    float2 rr = *(const float2*)(R + (long long)m * ldc + n);
                    v0 += rr.x; v1 += rr.y;
                }
                if (OUTH) {
                    __half2* outp = (__half2*)((__half*)Cv + (long long)m * ldc + n);
                    *outp = __floats2half2_rn(v0, v1);
                } else {
                    float2* outp = (float2*)((float*)Cv + (long long)m * ldc + n);
                    *outp = make_float2(v0, v1);
                }
            }
        }
    }
}

// ---------------- host orchestration ------------------------------------------
extern "C" void kernel_launch(void* const* d_in, const int* in_sizes, int n_in,
                              void* d_out, int out_size) {
    const float* x = (const float*)d_in[0];
    const float* ln1_g = (const float*)d_in[2];
    const float* ln1_b = (const float*)d_in[3];
    const float* qkv_w = (const float*)d_in[4];
    const float* qkv_b = (const float*)d_in[5];
    const float* dense_w = (const float*)d_in[6];
    const float* dense_b = (const float*)d_in[7];
    const float* ln2_g = (const float*)d_in[8];
    const float* ln2_b = (const float*)d_in[9];
    const float* fc_w = (const float*)d_in[10];
    const float* fc_b = (const float*)d_in[11];
    const float* proj_w = (const float*)d_in[12];
    const float* proj_b = (const float*)d_in[13];
    const float* lnf_g = (const float*)d_in[14];
    const float* lnf_b = (const float*)d_in[15];

    float* h;
    __half *lnb16, *qkv16, *ctx16, *fc16;
    __half *qkvw16, *densew16, *fcw16, *projw16;
    cudaGetSymbolAddress((void**)&h, g_h);
    cudaGetSymbolAddress((void**)&lnb16, g_lnb16);
    cudaGetSymbolAddress((void**)&qkv16, g_qkv16);
    cudaGetSymbolAddress((void**)&ctx16, g_ctx16);
    cudaGetSymbolAddress((void**)&fc16, g_fc16);
    cudaGetSymbolAddress((void**)&qkvw16, g_qkvw16);
    cudaGetSymbolAddress((void**)&densew16, g_densew16);
    cudaGetSymbolAddress((void**)&fcw16, g_fcw16);
    cudaGetSymbolAddress((void**)&projw16, g_projw16);

    const int SMH = NST * (BM * LDK * 2 + BK * (128 + 8) * 2);  // 71680
    cudaFuncSetAttribute(hgemm<128, 0>, cudaFuncAttributeMaxDynamicSharedMemorySize, SMH);
    cudaFuncSetAttribute(hgemm<128, 1>, cudaFuncAttributeMaxDynamicSharedMemorySize, SMH);
    cudaFuncSetAttribute(flash_attn, cudaFuncAttributeMaxDynamicSharedMemorySize, FSMT);

    // fp32 -> fp16 weight conversion, single fused launch
    long long totalW = W1 + W2 + W3 + W4;                // 25,165,824 elems
    convert_all<<<(int)(totalW / 1024), 256>>>(qkv_w, dense_w, fc_w, proj_w,
                                               qkvw16, densew16, fcw16, projw16);

    for (int l = 0; l < NLAYER; l++) {
        const float* hin = (l == 0) ? x : h;   // layer 0 reads input directly
        // LN1 -> fp16
        ln_kernel<__half><<<SQ, 256>>>(hin, ln1_g + l * HD, ln1_b + l * HD, lnb16);
        // QKV
        hgemm<128, 1><<<dim3(3 * HD / 128, SQ / BM), 256, SMH>>>(
            lnb16, HD, qkvw16 + (long long)l * HD * 3 * HD, 3 * HD,
            qkv_b + l * 3 * HD, nullptr, qkv16, 3 * HD, HD, 0);
        // fused attention
        flash_attn<<<dim3(SQ / 128, NHEAD), 256, FSMT>>>(qkv16, ctx16);
        // dense + residual -> fp32 h   (R = x for layer 0)
        hgemm<128, 0><<<dim3(HD / 128, SQ / BM), 256, SMH>>>(
            ctx16, HD, densew16 + (long long)l * HD * HD, HD,
            dense_b + l * HD, hin, h, HD, HD, 0);
        // LN2 -> fp16
        ln_kernel<__half><<<SQ, 256>>>(h, ln2_g + l * HD, ln2_b + l * HD, lnb16);
        // FC + gelu -> fp16
        hgemm<128, 1><<<dim3(4 * HD / 128, SQ / BM), 256, SMH>>>(
            lnb16, HD, fcw16 + (long long)l * HD * 4 * HD, 4 * HD,
            fc_b + l * 4 * HD, nullptr, fc16, 4 * HD, HD, 1);
        // proj + residual -> fp32 h
        hgemm<128, 0><<<dim3(HD / 128, SQ / BM), 256, SMH>>>(
            fc16, 4 * HD, projw16 + (long long)l * 4 * HD * HD, HD,
            proj_b + l * HD, h, h, HD, 4 * HD, 0);
    }
    ln_kernel<float><<<SQ, 256>>>(h, lnf_g, lnf_b, (float*)d_out);
}

// round 14
// speedup vs baseline: 1.0732x; 1.0732x over previous
#include <cuda_runtime.h>
#include <cuda_fp16.h>
#include <math.h>
#include <stdint.h>

#define SQ 2048
#define HD 1024
#define NHEAD 16
#define HNDIM 64
#define NLAYER 2

#define BM 128
#define BK 64      // halves per K-tile (GEMM)
#define LDK 72     // padded A smem row (halves)
#define NST 2      // GEMM pipeline stages

// flash attention tiles
#define FLDQ 72                       // padded row length (halves) for Q/K/V tiles
#define FKVB (128 * FLDQ * 2)         // bytes per 128x64 tile = 18432
#define FSTG (2 * FKVB)               // K+V per stage
#define FSMT (FKVB + 2 * FSTG)        // Q + 2 stages = 92160 B

// ---------------- scratch (device globals; no allocations allowed) ----------
__device__ float g_h[SQ * HD];                 // fp32 residual stream
__device__ __half g_lnb16[SQ * HD];
__device__ __half g_qkv16[SQ * 3 * HD];
__device__ __half g_ctx16[SQ * HD];
__device__ __half g_fc16[SQ * 4 * HD];
// fp16 weights, SAME [K,N] layout as the fp32 originals (convert only)
__device__ __half g_qkvw16[NLAYER * HD * 3 * HD];
__device__ __half g_densew16[NLAYER * HD * HD];
__device__ __half g_fcw16[NLAYER * HD * 4 * HD];
__device__ __half g_projw16[NLAYER * 4 * HD * HD];

// ---------------- helpers ----------------------------------------------------
__device__ __forceinline__ float gelu_f(float x) {
    return 0.5f * x * (1.0f + tanhf(0.7978845608028654f * x * (1.0f + 0.044715f * x * x)));
}

__device__ __forceinline__ void cp16h(uint32_t smem, const __half* g) {
    asm volatile("cp.async.ca.shared.global [%0], [%1], 16;\n" :: "r"(smem), "l"(g));
}

__device__ __forceinline__ void ldsm4(uint32_t* r, uint32_t addr) {
    asm volatile("ldmatrix.sync.aligned.m8n8.x4.shared.b16 {%0,%1,%2,%3}, [%4];"
                 : "=r"(r[0]), "=r"(r[1]), "=r"(r[2]), "=r"(r[3]) : "r"(addr));
}

__device__ __forceinline__ void ldsm4t(uint32_t* r, uint32_t addr) {
    asm volatile("ldmatrix.sync.aligned.m8n8.x4.trans.shared.b16 {%0,%1,%2,%3}, [%4];"
                 : "=r"(r[0]), "=r"(r[1]), "=r"(r[2]), "=r"(r[3]) : "r"(addr));
}

__device__ __forceinline__ void mma16(float* d, const uint32_t* a, const uint32_t* b) {
    asm volatile(
        "mma.sync.aligned.m16n8k16.row.col.f32.f16.f16.f32 "
        "{%0,%1,%2,%3}, {%4,%5,%6,%7}, {%8,%9}, {%0,%1,%2,%3};\n"
        : "+f"(d[0]), "+f"(d[1]), "+f"(d[2]), "+f"(d[3])
        : "r"(a[0]), "r"(a[1]), "r"(a[2]), "r"(a[3]), "r"(b[0]), "r"(b[1]));
}

__device__ __forceinline__ uint32_t packh2(float a, float b) {
    __half2 h = __floats2half2_rn(a, b);
    return *(uint32_t*)&h;
}

// ---------------- layernorm: one-pass, float4 I/O -----------------------------
template <typename OUT>
__global__ __launch_bounds__(256) void ln_kernel(const float* __restrict__ x,
                                                 const float* __restrict__ g,
                                                 const float* __restrict__ b,
                                                 OUT* __restrict__ out) {
    int row = blockIdx.x;
    const float* xr = x + (size_t)row * HD;
    OUT* outr = out + (size_t)row * HD;
    int t = threadIdx.x;
    __shared__ float red1[8], red2[8];

    float4 v = *(const float4*)(xr + t * 4);
    float s1 = v.x + v.y + v.z + v.w;
    float s2 = v.x * v.x + v.y * v.y + v.z * v.z + v.w * v.w;
#pragma unroll
    for (int o = 16; o > 0; o >>= 1) {
        s1 += __shfl_xor_sync(~0u, s1, o);
        s2 += __shfl_xor_sync(~0u, s2, o);
    }
    if ((t & 31) == 0) { red1[t >> 5] = s1; red2[t >> 5] = s2; }
    __syncthreads();
    s1 = 0.0f; s2 = 0.0f;
#pragma unroll
    for (int w = 0; w < 8; w++) { s1 += red1[w]; s2 += red2[w]; }
    float mu = s1 * (1.0f / HD);
    float var = s2 * (1.0f / HD) - mu * mu;
    float rstd = rsqrtf(var + 1e-5f);

    float4 gg = *(const float4*)(g + t * 4);
    float4 bb = *(const float4*)(b + t * 4);
    float o0 = (v.x - mu) * rstd * gg.x + bb.x;
    float o1 = (v.y - mu) * rstd * gg.y + bb.y;
    float o2 = (v.z - mu) * rstd * gg.z + bb.z;
    float o3 = (v.w - mu) * rstd * gg.w + bb.w;
    if (sizeof(OUT) == 2) {
        __half2 h0 = __floats2half2_rn(o0, o1);
        __half2 h1 = __floats2half2_rn(o2, o3);
        *(uint2*)((__half*)outr + t * 4) = make_uint2(*(uint32_t*)&h0, *(uint32_t*)&h1);
    } else {
        *(float4*)((float*)outr + t * 4) = make_float4(o0, o1, o2, o3);
    }
}

// ---------------- fused weight convert: all 4 arrays, one launch --------------
#define W1 ((long long)NLAYER * HD * 3 * HD)   // qkv
#define W2 ((long long)NLAYER * HD * HD)       // dense
#define W3 ((long long)NLAYER * HD * 4 * HD)   // fc
#define W4 ((long long)NLAYER * 4 * HD * HD)   // proj

__global__ __launch_bounds__(256) void convert_all(
    const float* __restrict__ qkv_w, const float* __restrict__ dense_w,
    const float* __restrict__ fc_w, const float* __restrict__ proj_w,
    __half* __restrict__ qkvh, __half* __restrict__ denseh,
    __half* __restrict__ fch, __half* __restrict__ projh) {
    long long i = ((long long)blockIdx.x * 256 + threadIdx.x) * 4;
    const float* src;
    __half* dst;
    if (i < W1) { src = qkv_w; dst = qkvh; }
    else if (i < W1 + W2) { i -= W1; src = dense_w; dst = denseh; }
    else if (i < W1 + W2 + W3) { i -= W1 + W2; src = fc_w; dst = fch; }
    else { i -= W1 + W2 + W3; src = proj_w; dst = projh; }
    float4 v = *(const float4*)(src + i);
    __half2 a = __floats2half2_rn(v.x, v.y);
    __half2 b = __floats2half2_rn(v.z, v.w);
    *(uint2*)(dst + i) = make_uint2(*(uint32_t*)&a, *(uint32_t*)&b);
}

// ---------------- fused flash attention ---------------------------------------
// grid: (SQ/128, NHEAD), block 256 (8 warps x 16 q-rows). KV tile = 128 keys.
// 2-stage, ONE __syncthreads per KV tile.
__global__ __launch_bounds__(256, 1) void flash_attn(
    const __half* __restrict__ qkv, __half* __restrict__ ctx) {
    extern __shared__ __align__(16) char fsm[];
    uint32_t sb;
    asm("{ .reg .u64 tmp; cvta.to.shared.u64 tmp, %1; cvt.u32.u64 %0, tmp; }"
        : "=r"(sb) : "l"(fsm));

    int qt = gridDim.x - 1 - blockIdx.x;   // heavy q-tiles first
    int hh = blockIdx.y;
    int ntiles = qt + 1;

    int t = threadIdx.x, w = t >> 5, lane = t & 31;
    int lrow = lane & 15, lcol = (lane >> 4) << 3;
    int g = lane >> 2, tig = lane & 3;

    const __half* Qg = qkv + (size_t)(qt * 128) * (3 * HD) + hh * HNDIM;
    const __half* Kg = qkv + HD + hh * HNDIM;
    const __half* Vg = qkv + 2 * HD + hh * HNDIM;

#define FLOADKV(j)                                                                 \
    {                                                                              \
        uint32_t base_ = sb + FKVB + ((j) & 1) * FSTG;                             \
        const __half* Kg_ = Kg + (size_t)((j) * 128) * (3 * HD);                   \
        const __half* Vg_ = Vg + (size_t)((j) * 128) * (3 * HD);                   \
        _Pragma("unroll") for (int i_ = 0; i_ < 4; i_++) {                         \
            int id_ = t + i_ * 256;                                                \
            int r_ = id_ >> 3, c_ = (id_ & 7) * 8;                                 \
            cp16h(base_ + (r_ * FLDQ + c_) * 2, Kg_ + (size_t)r_ * (3 * HD) + c_); \
            cp16h(base_ + FKVB + (r_ * FLDQ + c_) * 2,                             \
                  Vg_ + (size_t)r_ * (3 * HD) + c_);                               \
        }                                                                          \
        asm volatile("cp.async.commit_group;\n" ::: "memory");                     \
    }

    // group 0: Q + KV tile 0
#pragma unroll
    for (int i = 0; i < 4; i++) {
        int id = t + i * 256;
        int r = id >> 3, c = (id & 7) * 8;
        cp16h(sb + (r * FLDQ + c) * 2, Qg + (size_t)r * (3 * HD) + c);
    }
    FLOADKV(0);

    float m0 = -1e30f, m1 = -1e30f, l0 = 0.0f, l1 = 0.0f;
    float out[8][4] = {};
    uint32_t aq[4][4];

    int row0 = qt * 128 + w * 16 + g;
    int row1 = row0 + 8;

    for (int j = 0; j < ntiles; j++) {
        asm volatile("cp.async.wait_group 0;\n" ::: "memory");
        __syncthreads();
        if (j + 1 < ntiles) FLOADKV(j + 1);

        if (j == 0) {
#pragma unroll
            for (int kk = 0; kk < 4; kk++)
                ldsm4(aq[kk], sb + ((w * 16 + lrow) * FLDQ + kk * 16 + lcol) * 2);
        }

        uint32_t kb = sb + FKVB + (j & 1) * FSTG;
        uint32_t vb = kb + FKVB;

        // S = Q K^T
        float sacc[16][4] = {};
#pragma unroll
        for (int kk = 0; kk < 4; kk++) {
            uint32_t bk[16][2];
#pragma unroll
            for (int jp = 0; jp < 8; jp++) {
                uint32_t r4[4];
                ldsm4(r4, kb + ((jp * 16 + lrow) * FLDQ + kk * 16 + lcol) * 2);
                bk[2 * jp][0] = r4[0]; bk[2 * jp][1] = r4[2];
                bk[2 * jp + 1][0] = r4[1]; bk[2 * jp + 1][1] = r4[3];
            }
#pragma unroll
            for (int jn = 0; jn < 16; jn++) mma16(sacc[jn], aq[kk], bk[jn]);
        }

        // scale + causal mask + tile row-max
        bool diag = (j == qt);
        float tm0 = -1e30f, tm1 = -1e30f;
#pragma unroll
        for (int jn = 0; jn < 16; jn++) {
            int col = j * 128 + jn * 8 + tig * 2;
            float s0 = sacc[jn][0] * 0.125f, s1 = sacc[jn][1] * 0.125f;
            float s2 = sacc[jn][2] * 0.125f, s3 = sacc[jn][3] * 0.125f;
            if (diag) {
                if (col > row0) s0 = -10000.0f;
                if (col + 1 > row0) s1 = -10000.0f;
                if (col > row1) s2 = -10000.0f;
                if (col + 1 > row1) s3 = -10000.0f;
            }
            sacc[jn][0] = s0; sacc[jn][1] = s1; sacc[jn][2] = s2; sacc[jn][3] = s3;
            tm0 = fmaxf(tm0, fmaxf(s0, s1));
            tm1 = fmaxf(tm1, fmaxf(s2, s3));
        }
        tm0 = fmaxf(tm0, __shfl_xor_sync(~0u, tm0, 1));
        tm0 = fmaxf(tm0, __shfl_xor_sync(~0u, tm0, 2));
        tm1 = fmaxf(tm1, __shfl_xor_sync(~0u, tm1, 1));
        tm1 = fmaxf(tm1, __shfl_xor_sync(~0u, tm1, 2));

        float mn0 = fmaxf(m0, tm0), mn1 = fmaxf(m1, tm1);
        float c0 = __expf(m0 - mn0), c1 = __expf(m1 - mn1);
        l0 *= c0; l1 *= c1;
#pragma unroll
        for (int jo = 0; jo < 8; jo++) {
            out[jo][0] *= c0; out[jo][1] *= c0;
            out[jo][2] *= c1; out[jo][3] *= c1;
        }
        m0 = mn0; m1 = mn1;

        // P = exp(S - m) -> fp16 A-frags
        uint32_t pa[8][4];
#pragma unroll
        for (int kk2 = 0; kk2 < 8; kk2++) {
            float p00 = __expf(sacc[2 * kk2][0] - mn0);
            float p01 = __expf(sacc[2 * kk2][1] - mn0);
            float p02 = __expf(sacc[2 * kk2][2] - mn1);
            float p03 = __expf(sacc[2 * kk2][3] - mn1);
            float p10 = __expf(sacc[2 * kk2 + 1][0] - mn0);
            float p11 = __expf(sacc[2 * kk2 + 1][1] - mn0);
            float p12 = __expf(sacc[2 * kk2 + 1][2] - mn1);
            float p13 = __expf(sacc[2 * kk2 + 1][3] - mn1);
            l0 += p00 + p01 + p10 + p11;
            l1 += p02 + p03 + p12 + p13;
            pa[kk2][0] = packh2(p00, p01);
            pa[kk2][1] = packh2(p02, p03);
            pa[kk2][2] = packh2(p10, p11);
            pa[kk2][3] = packh2(p12, p13);
        }

        // out += P V   (V via ldmatrix.trans from [s][d])
#pragma unroll
        for (int kk2 = 0; kk2 < 8; kk2++) {
            uint32_t bv[8][2];
#pragma unroll
            for (int jp = 0; jp < 4; jp++) {
                uint32_t r4[4];
                ldsm4t(r4, vb + ((kk2 * 16 + lrow) * FLDQ + jp * 16 + lcol) * 2);
                bv[2 * jp][0] = r4[0]; bv[2 * jp][1] = r4[1];
                bv[2 * jp + 1][0] = r4[2]; bv[2 * jp + 1][1] = r4[3];
            }
#pragma unroll
            for (int jo = 0; jo < 8; jo++) mma16(out[jo], pa[kk2], bv[jo]);
        }
    }
#undef FLOADKV

    // finalize
    l0 += __shfl_xor_sync(~0u, l0, 1);
    l0 += __shfl_xor_sync(~0u, l0, 2);
    l1 += __shfl_xor_sync(~0u, l1, 1);
    l1 += __shfl_xor_sync(~0u, l1, 2);
    float r0 = 1.0f / l0, r1 = 1.0f / l1;

#pragma unroll
    for (int jo = 0; jo < 8; jo++) {
        int d = hh * HNDIM + jo * 8 + tig * 2;
        __half2 o0 = __floats2half2_rn(out[jo][0] * r0, out[jo][1] * r0);
        __half2 o1 = __floats2half2_rn(out[jo][2] * r1, out[jo][3] * r1);
        *(__half2*)(ctx + (size_t)row0 * HD + d) = o0;
        *(__half2*)(ctx + (size_t)row1 * HD + d) = o1;
    }
}

// ---------------- fp16 tensor-core GEMM (linear layers) -----------------------
// A [M,K] row-major; B [K,N] row-major (natural weight layout) via ldsm.trans.
// BK=64, 2-stage, ONE __syncthreads per K-tile.
template <int TBN, int OUTH>
__global__ __launch_bounds__(256, 2) void hgemm(
    const __half* __restrict__ A, int lda,
    const __half* __restrict__ B, int ldb,
    const float* __restrict__ bias,
    const float* __restrict__ R,
    void* __restrict__ Cv, int ldc,
    int K, int act) {
    constexpr int NF = TBN / 16;
    constexpr int LDB = TBN + 8;
    constexpr int ASZ = BM * LDK * 2;
    constexpr int BSZ = BK * LDB * 2;
    constexpr int STB = ASZ + BSZ;
    constexpr int A_CP = (BM * BK / 8) / 256;
    constexpr int B_CP = (BK * TBN / 8) / 256;
    constexpr int BCHUNK = TBN / 8;

    extern __shared__ __align__(16) char smem[];
    uint32_t sb;
    asm("{ .reg .u64 tmp; cvta.to.shared.u64 tmp, %1; cvt.u32.u64 %0, tmp; }"
        : "=r"(sb) : "l"(smem));

    int m0 = blockIdx.y * BM;
    int n0 = blockIdx.x * TBN;
    int T = K / BK;

    int t = threadIdx.x;
    int wid = t >> 5, lane = t & 31;
    int g = lane >> 2, tig = lane & 3;
    int wm = (wid & 3) * 32;
    int wn = (wid >> 2) * (TBN / 2);

    const __half* Ag0 = A + (long long)m0 * lda;
    const __half* Bg0 = B + n0;

    float acc[2][NF][4] = {};

#define LOADST(ti)                                                                \
    {                                                                             \
        uint32_t as_ = sb + ((ti) & 1) * STB;                                     \
        uint32_t bs_ = as_ + ASZ;                                                 \
        const __half* Ag_ = Ag0 + (long long)(ti) * BK;                           \
        const __half* Bg_ = Bg0 + (long long)(ti) * BK * ldb;                     \
        _Pragma("unroll") for (int i = 0; i < A_CP; i++) {                        \
            int id = t + i * 256;                                                 \
            int r = id >> 3, c = (id & 7) * 8;                                    \
            cp16h(as_ + (r * LDK + c) * 2, Ag_ + (long long)r * lda + c);         \
        }                                                                         \
        _Pragma("unroll") for (int i = 0; i < B_CP; i++) {                        \
            int id = t + i * 256;                                                 \
            int r = id / BCHUNK, c = (id % BCHUNK) * 8;                           \
            cp16h(bs_ + (r * LDB + c) * 2, Bg_ + (long long)r * ldb + c);         \
        }                                                                         \
        asm volatile("cp.async.commit_group;\n" ::: "memory");                    \
    }

    LOADST(0);

    int lrow = lane & 15, lcol = (lane >> 4) << 3;

    for (int ti = 0; ti < T; ti++) {
        asm volatile("cp.async.wait_group 0;\n" ::: "memory");
        __syncthreads();
        if (ti + 1 < T) LOADST(ti + 1);

        uint32_t as = sb + (ti & 1) * STB;
        uint32_t bs = as + ASZ;

#pragma unroll
        for (int kk = 0; kk < 4; kk++) {
            int k16 = kk * 16;
            uint32_t a[2][4];
#pragma unroll
            for (int f = 0; f < 2; f++)
                ldsm4(a[f], as + ((wm + f * 16 + lrow) * LDK + k16 + lcol) * 2);
            uint32_t bf[NF][2];
#pragma unroll
            for (int jp = 0; jp < NF / 2; jp++) {
                uint32_t r4[4];
                ldsm4t(r4, bs + ((k16 + lrow) * LDB + wn + jp * 16 + lcol) * 2);
                bf[2 * jp][0] = r4[0]; bf[2 * jp][1] = r4[1];
                bf[2 * jp + 1][0] = r4[2]; bf[2 * jp + 1][1] = r4[3];
            }
#pragma unroll
            for (int f = 0; f < 2; f++)
#pragma unroll
                for (int j = 0; j < NF; j++) mma16(acc[f][j], a[f], bf[j]);
        }
    }
#undef LOADST

#pragma unroll
    for (int f = 0; f < 2; f++) {
#pragma unroll
        for (int j = 0; j < NF; j++) {
            int n = n0 + wn + j * 8 + tig * 2;
#pragma unroll
            for (int half_ = 0; half_ < 2; half_++) {
                int m = m0 + wm + f * 16 + g + half_ * 8;
                float v0 = acc[f][j][half_ * 2 + 0];
                float v1 = acc[f][j][half_ * 2 + 1];
                if (bias) {
                    float2 bb = *(const float2*)(bias + n);
                    v0 += bb.x; v1 += bb.y;
                }
                if (act) { v0 = gelu_f(v0); v1 = gelu_f(v1); }
                if (R) {
                    float2 rr = *(const float2*)(R + (long long)m * ldc + n);
                    v0 += rr.x; v1 += rr.y;
                }
                if (OUTH) {
                    __half2* outp = (__half2*)((__half*)Cv + (long long)m * ldc + n);
                    *outp = __floats2half2_rn(v0, v1);
                } else {
                    float2* outp = (float2*)((float*)Cv + (long long)m * ldc + n);
                    *outp = make_float2(v0, v1);
                }
            }
        }
    }
}

// ---------------- host orchestration ------------------------------------------
extern "C" void kernel_launch(void* const* d_in, const int* in_sizes, int n_in,
                              void* d_out, int out_size) {
    const float* x = (const float*)d_in[0];
    const float* ln1_g = (const float*)d_in[2];
    const float* ln1_b = (const float*)d_in[3];
    const float* qkv_w = (const float*)d_in[4];
    const float* qkv_b = (const float*)d_in[5];
    const float* dense_w = (const float*)d_in[6];
    const float* dense_b = (const float*)d_in[7];
    const float* ln2_g = (const float*)d_in[8];
    const float* ln2_b = (const float*)d_in[9];
    const float* fc_w = (const float*)d_in[10];
    const float* fc_b = (const float*)d_in[11];
    const float* proj_w = (const float*)d_in[12];
    const float* proj_b = (const float*)d_in[13];
    const float* lnf_g = (const float*)d_in[14];
    const float* lnf_b = (const float*)d_in[15];

    float* h;
    __half *lnb16, *qkv16, *ctx16, *fc16;
    __half *qkvw16, *densew16, *fcw16, *projw16;
    cudaGetSymbolAddress((void**)&h, g_h);
    cudaGetSymbolAddress((void**)&lnb16, g_lnb16);
    cudaGetSymbolAddress((void**)&qkv16, g_qkv16);
    cudaGetSymbolAddress((void**)&ctx16, g_ctx16);
    cudaGetSymbolAddress((void**)&fc16, g_fc16);
    cudaGetSymbolAddress((void**)&qkvw16, g_qkvw16);
    cudaGetSymbolAddress((void**)&densew16, g_densew16);
    cudaGetSymbolAddress((void**)&fcw16, g_fcw16);
    cudaGetSymbolAddress((void**)&projw16, g_projw16);

    const int SMH = NST * (BM * LDK * 2 + BK * (128 + 8) * 2);  // 71680
    cudaFuncSetAttribute(hgemm<128, 0>, cudaFuncAttributeMaxDynamicSharedMemorySize, SMH);
    cudaFuncSetAttribute(hgemm<128, 1>, cudaFuncAttributeMaxDynamicSharedMemorySize, SMH);
    cudaFuncSetAttribute(flash_attn, cudaFuncAttributeMaxDynamicSharedMemorySize, FSMT);

    // fp32 -> fp16 weight conversion, single fused launch
    long long totalW = W1 + W2 + W3 + W4;                // 25,165,824 elems
    convert_all<<<(int)(totalW / 1024), 256>>>(qkv_w, dense_w, fc_w, proj_w,
                                               qkvw16, densew16, fcw16, projw16);

    for (int l = 0; l < NLAYER; l++) {
        const float* hin = (l == 0) ? x : h;   // layer 0 reads input directly
        // LN1 -> fp16
        ln_kernel<__half><<<SQ, 256>>>(hin, ln1_g + l * HD, ln1_b + l * HD, lnb16);
        // QKV
        hgemm<128, 1><<<dim3(3 * HD / 128, SQ / BM), 256, SMH>>>(
            lnb16, HD, qkvw16 + (long long)l * HD * 3 * HD, 3 * HD,
            qkv_b + l * 3 * HD, nullptr, qkv16, 3 * HD, HD, 0);
        // fused attention
        flash_attn<<<dim3(SQ / 128, NHEAD), 256, FSMT>>>(qkv16, ctx16);
        // dense + residual -> fp32 h   (R = x for layer 0)
        hgemm<128, 0><<<dim3(HD / 128, SQ / BM), 256, SMH>>>(
            ctx16, HD, densew16 + (long long)l * HD * HD, HD,
            dense_b + l * HD, hin, h, HD, HD, 0);
        // LN2 -> fp16
        ln_kernel<__half><<<SQ, 256>>>(h, ln2_g + l * HD, ln2_b + l * HD, lnb16);
        // FC + gelu -> fp16
        hgemm<128, 1><<<dim3(4 * HD / 128, SQ / BM), 256, SMH>>>(
            lnb16, HD, fcw16 + (long long)l * HD * 4 * HD, 4 * HD,
            fc_b + l * 4 * HD, nullptr, fc16, 4 * HD, HD, 1);
        // proj + residual -> fp32 h
        hgemm<128, 0><<<dim3(HD / 128, SQ / BM), 256, SMH>>>(
            fc16, 4 * HD, projw16 + (long long)l * 4 * HD * HD, HD,
            proj_b + l * HD, h, h, HD, 4 * HD, 0);
    }
    ln_kernel<float><<<SQ, 256>>>(h, lnf_g, lnf_b, (float*)d_out);
}